// round 15
// baseline (speedup 1.0000x reference)
#include <cuda_runtime.h>
#include <cuda_bf16.h>

// Problem constants
#define NPART    148     // persistent CTAs (one per SM)
#define NCHUNK1  4096    // K1: chunks of 64 points  (262144/64);  b = chunk>>10
#define NCHUNK3  2048    // K3: chunks of 128 points (262144/128); b = chunk>>9

// Deterministic scratch (no cudaMalloc allowed)
__device__ float g_part[4 * NPART * 4096];   // per-CTA partial kv  [b][cta][h*1024+d*32+e]
__device__ float g_kv[4 * 4096];             // reduced kv          [b][h*1024+d*32+e]
__device__ float g_wqeff[4 * 16384];         // folded weights      [b][n*128 + c]  (n = e*4+h)
// Pre-converted X tiles: per 64-pt chunk, 32 KB = [hi 16K][lo 16K], swizzled.
__device__ char  g_xbf[(size_t)NCHUNK1 * 32768];

// ---- cp.async helpers ----
__device__ __forceinline__ void cp16(void* smem_dst, const void* gsrc) {
    unsigned s = (unsigned)__cvta_generic_to_shared(smem_dst);
    asm volatile("cp.async.cg.shared.global [%0], [%1], 16;" :: "r"(s), "l"(gsrc));
}
__device__ __forceinline__ void cp_commit() {
    asm volatile("cp.async.commit_group;");
}
__device__ __forceinline__ void cp_wait1() {
    asm volatile("cp.async.wait_group 1;");
}

__device__ __forceinline__ unsigned bf2u(__nv_bfloat162 v) {
    return *reinterpret_cast<unsigned*>(&v);
}

// ---- shared mma.sync infrastructure ----
// bf16 tile [rows][256 bytes], XOR-swizzled at 16B granularity.
__device__ __forceinline__ unsigned sw_off(int row, int kbyte) {
    return (unsigned)((row << 8) + (kbyte ^ ((row & 7) << 4)));
}
// bf16 kn/vn tile [64 rows][512 bytes], XOR-swizzled at 16B granularity.
__device__ __forceinline__ unsigned skvb_off(int row, int chb) {
    return (unsigned)((row << 9) + (chb ^ ((row & 7) << 4)));
}

__device__ __forceinline__ void mma_bf16(float* c,
                                         unsigned a0, unsigned a1, unsigned a2, unsigned a3,
                                         unsigned b0, unsigned b1) {
    asm volatile(
        "mma.sync.aligned.m16n8k16.row.col.f32.bf16.bf16.f32 "
        "{%0,%1,%2,%3}, {%4,%5,%6,%7}, {%8,%9}, {%0,%1,%2,%3};"
        : "+f"(c[0]), "+f"(c[1]), "+f"(c[2]), "+f"(c[3])
        : "r"(a0), "r"(a1), "r"(a2), "r"(a3), "r"(b0), "r"(b1));
}

__device__ __forceinline__ void ldsm4(unsigned* r, unsigned a) {
    asm volatile("ldmatrix.sync.aligned.m8n8.x4.shared.b16 {%0,%1,%2,%3}, [%4];"
                 : "=r"(r[0]), "=r"(r[1]), "=r"(r[2]), "=r"(r[3]) : "r"(a));
}
__device__ __forceinline__ void ldsm4t(unsigned* r, unsigned a) {
    asm volatile("ldmatrix.sync.aligned.m8n8.x4.trans.shared.b16 {%0,%1,%2,%3}, [%4];"
                 : "=r"(r[0]), "=r"(r[1]), "=r"(r[2]), "=r"(r[3]) : "r"(a));
}

// ============================================================================
// Kernel 1 (r14 balanced + g_xbf export): ALL 16 warps do proj MMA (16x64,
// bf16x3) + 16x16 tensor outer slice + shared LN/store/X-staging. The X tile
// conversions are additionally streamed to g_xbf for K3's direct consumption.
// smem: WT 128K | XT 32K | KVH 32K | KVL 32K | partk 1K | partv 1K = 226 KB
// ============================================================================
#define K1_WT_HI  0
#define K1_WT_LO  65536
#define K1_XT     131072     // hi at +0 (16K), lo at +16384 (16K)
#define K1_KVH    163840     // [64 pt][256 ch] bf16 hi (32K)
#define K1_KVL    196608     // lo (32K)
#define K1_PARTK  229376
#define K1_PARTV  230400
#define K1_SMEM   231424

__global__ void __launch_bounds__(512, 1)
k1_kv_mma(const float* __restrict__ X,
          const float* __restrict__ Wk, const float* __restrict__ Wv,
          const float* __restrict__ gamma, const float* __restrict__ beta)
{
    extern __shared__ char smem[];
    char* wth = smem + K1_WT_HI;
    char* wtl = smem + K1_WT_LO;
    char* xt  = smem + K1_XT;
    char* kvh = smem + K1_KVH;
    char* kvl = smem + K1_KVL;
    float2* partk = (float2*)(smem + K1_PARTK);
    float2* partv = (float2*)(smem + K1_PARTV);

    const unsigned xt_u  = (unsigned)__cvta_generic_to_shared(xt);
    const unsigned wth_u = (unsigned)__cvta_generic_to_shared(wth);
    const unsigned kvh_u = (unsigned)__cvta_generic_to_shared(kvh);

    const int tid  = threadIdx.x;
    const int lane = tid & 31;
    const int warp = tid >> 5;
    const int qr = lane >> 2;
    const int qc = lane & 3;

    // ---- One-time: transpose + bf16-split Wk|Wv into WT tiles ----
    for (int idx = tid; idx < 4096; idx += 512) {
        const int c  = idx >> 5;
        const int n4 = (idx & 31) << 2;
        const float4 wk = ((const float4*)Wk)[idx];
        const float4 wv = ((const float4*)Wv)[idx];
#pragma unroll
        for (int j = 0; j < 4; j++) {
            const float vk = (&wk.x)[j];
            const float vv = (&wv.x)[j];
            __nv_bfloat16 hk = __float2bfloat16(vk);
            __nv_bfloat16 hv = __float2bfloat16(vv);
            __nv_bfloat16 lk = __float2bfloat16(vk - __bfloat162float(hk));
            __nv_bfloat16 lv = __float2bfloat16(vv - __bfloat162float(hv));
            const unsigned ok = sw_off(n4 + j,       c * 2);
            const unsigned ov = sw_off(128 + n4 + j, c * 2);
            *(__nv_bfloat16*)(wth + ok) = hk;
            *(__nv_bfloat16*)(wtl + ok) = lk;
            *(__nv_bfloat16*)(wth + ov) = hv;
            *(__nv_bfloat16*)(wtl + ov) = lv;
        }
    }

    // ---- proj tile: 16 rows x 64 cols over the 64 x 256 (k|v) output ----
    const int m0  = (warp & 3) * 16;
    const int n0g = (warp >> 2) * 64;
    const int kw  = (n0g < 128);
    const int cg  = (warp >> 2) & 1;

    float gv[8], bv[8], gv1[8], bv1[8];
#pragma unroll
    for (int nj = 0; nj < 8; nj++) {
        const int ch = (n0g + nj * 8 + qc * 2) & 127;
        gv[nj] = gamma[ch];  bv[nj] = beta[ch];
        gv1[nj] = gamma[(ch + 1) & 127]; bv1[nj] = beta[(ch + 1) & 127];
    }

    const int laneK = lane & 16;
    const int bKoff = (lane & 8) << 1;
    unsigned aBase, aSw, bBase[4], bSw[4];
    {
        const int row = m0 + (lane & 15);
        aSw = (unsigned)((row & 7) << 4);
        aBase = xt_u + row * 256;
    }
#pragma unroll
    for (int p = 0; p < 4; p++) {
        const int row = n0g + p * 16 + ((lane >> 1) & 8) + (lane & 7);
        bSw[p] = (unsigned)((row & 7) << 4);
        bBase[p] = wth_u + row * 256;
    }

    // ---- outer slice: head hh2, d-half dh, e-half eh (16x16 kv tile) ----
    const int hh2 = warp >> 2;
    const int dh  = (warp >> 1) & 1;
    const int eh  = warp & 1;
    const int rkA = (lane & 7) + ((lane >> 4) & 1) * 8;
    const unsigned chbA = (unsigned)(hh2 * 64 + dh * 32 + ((lane >> 3) & 1) * 16);
    const unsigned aOut = kvh_u + rkA * 512 + (chbA ^ ((unsigned)(rkA & 7) << 4));
    const int rkB = (lane & 7) + ((lane >> 3) & 1) * 8;
    const unsigned swB = (unsigned)(rkB & 7) << 4;
    const unsigned chbB = (unsigned)(256 + hh2 * 64 + eh * 32 + ((lane >> 4) & 1) * 16);
    const unsigned bOut = kvh_u + rkB * 512 + (chbB ^ swB);

    float co[2][4];
#pragma unroll
    for (int nt = 0; nt < 2; nt++)
#pragma unroll
        for (int z = 0; z < 4; z++) co[nt][z] = 0.f;

    // ---- X staging (+ gmem export of converted tiles) ----
    float4 xr[4];
    const int chunk0 = blockIdx.x;
    {
        const float4* src = (const float4*)X + (size_t)chunk0 * 2048;
#pragma unroll
        for (int i = 0; i < 4; i++) xr[i] = src[tid + i * 512];
        char* gx = g_xbf + (size_t)chunk0 * 32768;
#pragma unroll
        for (int i = 0; i < 4; i++) {
            const int idx = tid + i * 512;
            const int row = idx >> 5;
            const int kb  = (idx & 31) << 3;
            const float4 x = xr[i];
            __nv_bfloat162 h0 = __floats2bfloat162_rn(x.x, x.y);
            __nv_bfloat162 h1 = __floats2bfloat162_rn(x.z, x.w);
            float2 f0 = __bfloat1622float2(h0);
            float2 f1 = __bfloat1622float2(h1);
            __nv_bfloat162 l0 = __floats2bfloat162_rn(x.x - f0.x, x.y - f0.y);
            __nv_bfloat162 l1 = __floats2bfloat162_rn(x.z - f1.x, x.w - f1.y);
            const unsigned off = sw_off(row, kb);
            *(__nv_bfloat162*)(xt + off)             = h0;
            *(__nv_bfloat162*)(xt + off + 4)         = h1;
            *(__nv_bfloat162*)(xt + 16384 + off)     = l0;
            *(__nv_bfloat162*)(xt + 16384 + off + 4) = l1;
            *(uint2*)(gx + off)         = make_uint2(bf2u(h0), bf2u(h1));
            *(uint2*)(gx + 16384 + off) = make_uint2(bf2u(l0), bf2u(l1));
        }
        const int c1 = chunk0 + NPART;
        if (c1 < NCHUNK1) {
            const float4* s1 = (const float4*)X + (size_t)c1 * 2048;
#pragma unroll
            for (int i = 0; i < 4; i++) xr[i] = s1[tid + i * 512];
        }
    }
    __syncthreads();

    int pend = -1, ob = -1;
    float c[8][4];

    for (int chunk = chunk0; chunk < NCHUNK1; chunk += NPART) {
        // ============ PHASE A: outer(i-1) + proj MMA(i) + LN partials ========
        if (pend >= 0) {
            const int bj = pend >> 10;
            if (bj != ob) {
                if (ob >= 0) {
                    float* dst = g_part + ((size_t)ob * NPART + blockIdx.x) * 4096
                               + hh2 * 1024 + (dh * 16 + qr) * 32 + eh * 16 + qc * 2;
#pragma unroll
                    for (int nt = 0; nt < 2; nt++) {
                        *(float2*)(dst + nt * 8)          = make_float2(co[nt][0], co[nt][1]);
                        *(float2*)(dst + 8 * 32 + nt * 8) = make_float2(co[nt][2], co[nt][3]);
#pragma unroll
                        for (int z = 0; z < 4; z++) co[nt][z] = 0.f;
                    }
                }
                ob = bj;
            }
#pragma unroll
            for (int ks = 0; ks < 4; ks++) {
                const unsigned off = (unsigned)(ks * 8192);
                unsigned Ah[4], Al[4], Bh[4], Bl[4];
                ldsm4t(Ah, aOut + off);
                ldsm4t(Al, aOut + 32768u + off);
                ldsm4t(Bh, bOut + off);
                ldsm4t(Bl, bOut + 32768u + off);
                mma_bf16(co[0], Ah[0], Ah[1], Ah[2], Ah[3], Bh[0], Bh[1]);
                mma_bf16(co[0], Ah[0], Ah[1], Ah[2], Ah[3], Bl[0], Bl[1]);
                mma_bf16(co[0], Al[0], Al[1], Al[2], Al[3], Bh[0], Bh[1]);
                mma_bf16(co[1], Ah[0], Ah[1], Ah[2], Ah[3], Bh[2], Bh[3]);
                mma_bf16(co[1], Ah[0], Ah[1], Ah[2], Ah[3], Bl[2], Bl[3]);
                mma_bf16(co[1], Al[0], Al[1], Al[2], Al[3], Bh[2], Bh[3]);
            }
        }

        // ---- proj MMA (bf16x3), 16x64 tile ----
#pragma unroll
        for (int nj = 0; nj < 8; nj++)
#pragma unroll
            for (int z = 0; z < 4; z++) c[nj][z] = 0.f;

#pragma unroll
        for (int ks = 0; ks < 8; ks++) {
            const int kb = ks * 32;
            unsigned ah[4], al[4];
            {
                const unsigned off = (unsigned)(kb + laneK) ^ aSw;
                ldsm4(ah, aBase + off);
                ldsm4(al, aBase + 16384u + off);
            }
#pragma unroll
            for (int p = 0; p < 4; p++) {
                const unsigned off = (unsigned)(kb + bKoff) ^ bSw[p];
                unsigned th[4], tl[4];
                ldsm4(th, bBase[p] + off);
                ldsm4(tl, bBase[p] + 65536u + off);
                float* c0 = c[2 * p];
                float* c1 = c[2 * p + 1];
                mma_bf16(c0, ah[0], ah[1], ah[2], ah[3], th[0], th[1]);
                mma_bf16(c0, ah[0], ah[1], ah[2], ah[3], tl[0], tl[1]);
                mma_bf16(c0, al[0], al[1], al[2], al[3], th[0], th[1]);
                mma_bf16(c1, ah[0], ah[1], ah[2], ah[3], th[2], th[3]);
                mma_bf16(c1, ah[0], ah[1], ah[2], ah[3], tl[2], tl[3]);
                mma_bf16(c1, al[0], al[1], al[2], al[3], th[2], th[3]);
            }
        }

        // ---- LN partial stats ----
#pragma unroll
        for (int half = 0; half < 2; half++) {
            float s = 0.f, q = 0.f;
#pragma unroll
            for (int nj = 0; nj < 8; nj++) {
                const float v0 = c[nj][half * 2];
                const float v1 = c[nj][half * 2 + 1];
                s += v0 + v1;
                q += v0 * v0 + v1 * v1;
            }
            s += __shfl_xor_sync(0xffffffffu, s, 1);
            q += __shfl_xor_sync(0xffffffffu, q, 1);
            s += __shfl_xor_sync(0xffffffffu, s, 2);
            q += __shfl_xor_sync(0xffffffffu, q, 2);
            if (qc == 0) {
                const int row = m0 + half * 8 + qr;
                (kw ? partk : partv)[row * 2 + cg] = make_float2(s, q);
            }
        }
        __syncthreads();   // bar1

        // ============ PHASE B: normalize + store + X staging ================
        {
            const float2* pk = kw ? partk : partv;
#pragma unroll
            for (int half = 0; half < 2; half++) {
                const int row = m0 + half * 8 + qr;
                const float2 p0 = pk[row * 2];
                const float2 p1 = pk[row * 2 + 1];
                const float mu = (p0.x + p1.x) * (1.f / 128.f);
                const float ms = (p0.y + p1.y) * (1.f / 128.f);
                const float rr = rsqrtf(ms - mu * mu + 1e-5f);
                const float mm = -mu * rr;
#pragma unroll
                for (int nj = 0; nj < 8; nj++) {
                    float& v0 = c[nj][half * 2];
                    float& v1 = c[nj][half * 2 + 1];
                    v0 = fmaf(fmaf(v0, rr, mm), gv[nj], bv[nj]);
                    v1 = fmaf(fmaf(v1, rr, mm), gv1[nj], bv1[nj]);
                }
            }
#pragma unroll
            for (int nj = 0; nj < 8; nj++) {
                const int chb = (n0g + nj * 8 + qc * 2) * 2;
                __nv_bfloat162 h0 = __floats2bfloat162_rn(c[nj][0], c[nj][1]);
                float2 hf0 = __bfloat1622float2(h0);
                __nv_bfloat162 l0 = __floats2bfloat162_rn(c[nj][0] - hf0.x,
                                                          c[nj][1] - hf0.y);
                __nv_bfloat162 h1 = __floats2bfloat162_rn(c[nj][2], c[nj][3]);
                float2 hf1 = __bfloat1622float2(h1);
                __nv_bfloat162 l1 = __floats2bfloat162_rn(c[nj][2] - hf1.x,
                                                          c[nj][3] - hf1.y);
                const unsigned o0 = skvb_off(m0 + qr,     chb);
                const unsigned o1 = skvb_off(m0 + 8 + qr, chb);
                *(__nv_bfloat162*)(kvh + o0) = h0;
                *(__nv_bfloat162*)(kvl + o0) = l0;
                *(__nv_bfloat162*)(kvh + o1) = h1;
                *(__nv_bfloat162*)(kvl + o1) = l1;
            }
        }
        // cvt X(i+1) regs -> XT + gmem export; prefetch X(i+2)
        {
            const int nxt = chunk + NPART;
            if (nxt < NCHUNK1) {
                char* gx = g_xbf + (size_t)nxt * 32768;
#pragma unroll
                for (int i = 0; i < 4; i++) {
                    const int idx = tid + i * 512;
                    const int row = idx >> 5;
                    const int kb  = (idx & 31) << 3;
                    const float4 x = xr[i];
                    __nv_bfloat162 h0 = __floats2bfloat162_rn(x.x, x.y);
                    __nv_bfloat162 h1 = __floats2bfloat162_rn(x.z, x.w);
                    float2 f0 = __bfloat1622float2(h0);
                    float2 f1 = __bfloat1622float2(h1);
                    __nv_bfloat162 l0 = __floats2bfloat162_rn(x.x - f0.x, x.y - f0.y);
                    __nv_bfloat162 l1 = __floats2bfloat162_rn(x.z - f1.x, x.w - f1.y);
                    const unsigned off = sw_off(row, kb);
                    *(__nv_bfloat162*)(xt + off)             = h0;
                    *(__nv_bfloat162*)(xt + off + 4)         = h1;
                    *(__nv_bfloat162*)(xt + 16384 + off)     = l0;
                    *(__nv_bfloat162*)(xt + 16384 + off + 4) = l1;
                    *(uint2*)(gx + off)         = make_uint2(bf2u(h0), bf2u(h1));
                    *(uint2*)(gx + 16384 + off) = make_uint2(bf2u(l0), bf2u(l1));
                }
                const int nxt2 = nxt + NPART;
                if (nxt2 < NCHUNK1) {
                    const float4* src = (const float4*)X + (size_t)nxt2 * 2048;
#pragma unroll
                    for (int i = 0; i < 4; i++) xr[i] = src[tid + i * 512];
                }
            }
        }
        pend = chunk;
        __syncthreads();   // bar2
    }

    // Epilogue: outer for the final chunk, then flush
    if (pend >= 0) {
        const int bj = pend >> 10;
        if (bj != ob) {
            if (ob >= 0) {
                float* dst = g_part + ((size_t)ob * NPART + blockIdx.x) * 4096
                           + hh2 * 1024 + (dh * 16 + qr) * 32 + eh * 16 + qc * 2;
#pragma unroll
                for (int nt = 0; nt < 2; nt++) {
                    *(float2*)(dst + nt * 8)          = make_float2(co[nt][0], co[nt][1]);
                    *(float2*)(dst + 8 * 32 + nt * 8) = make_float2(co[nt][2], co[nt][3]);
#pragma unroll
                    for (int z = 0; z < 4; z++) co[nt][z] = 0.f;
                }
            }
            ob = bj;
        }
#pragma unroll
        for (int ks = 0; ks < 4; ks++) {
            const unsigned off = (unsigned)(ks * 8192);
            unsigned Ah[4], Al[4], Bh[4], Bl[4];
            ldsm4t(Ah, aOut + off);
            ldsm4t(Al, aOut + 32768u + off);
            ldsm4t(Bh, bOut + off);
            ldsm4t(Bl, bOut + 32768u + off);
            mma_bf16(co[0], Ah[0], Ah[1], Ah[2], Ah[3], Bh[0], Bh[1]);
            mma_bf16(co[0], Ah[0], Ah[1], Ah[2], Ah[3], Bl[0], Bl[1]);
            mma_bf16(co[0], Al[0], Al[1], Al[2], Al[3], Bh[0], Bh[1]);
            mma_bf16(co[1], Ah[0], Ah[1], Ah[2], Ah[3], Bh[2], Bh[3]);
            mma_bf16(co[1], Ah[0], Ah[1], Ah[2], Ah[3], Bl[2], Bl[3]);
            mma_bf16(co[1], Al[0], Al[1], Al[2], Al[3], Bh[2], Bh[3]);
        }
        float* dst = g_part + ((size_t)ob * NPART + blockIdx.x) * 4096
                   + hh2 * 1024 + (dh * 16 + qr) * 32 + eh * 16 + qc * 2;
#pragma unroll
        for (int nt = 0; nt < 2; nt++) {
            *(float2*)(dst + nt * 8)          = make_float2(co[nt][0], co[nt][1]);
            *(float2*)(dst + 8 * 32 + nt * 8) = make_float2(co[nt][2], co[nt][3]);
        }
    }
}

// ============================================================================
// Kernel 2a: reduce 148 per-CTA partials -> g_kv.
// ============================================================================
__global__ void k2a_reduce()
{
    const int gid = blockIdx.x * 256 + threadIdx.x;
    const int b = gid >> 12;
    const int e = gid & 4095;
    const float* src = g_part + (size_t)b * NPART * 4096 + e;
    float s = 0.f;
#pragma unroll 4
    for (int j = 0; j < NPART; j++) s += src[(size_t)j * 4096];
    g_kv[gid] = s;
}

// ============================================================================
// Kernel 2b: Wq_eff[b][n][c] = (1/N) * sum_d Wq[c][h*32+d] * kv[b][h][d][e]
// ============================================================================
__global__ void k2b_fold(const float* __restrict__ Wq)
{
    const int gid = blockIdx.x * 256 + threadIdx.x;
    const int b  = gid >> 14;
    const int r  = gid & 16383;
    const int cp = r >> 7;
    const int co = r & 127;
    const int e  = co >> 2;
    const int h  = co & 3;
    const float* wq = Wq + cp * 128 + h * 32;
    const float* kv = g_kv + b * 4096 + h * 1024 + e;
    float s = 0.f;
#pragma unroll
    for (int d = 0; d < 32; d++) s += wq[d] * kv[d * 32];
    g_wqeff[b * 16384 + co * 128 + cp] = s * (1.f / 65536.f);
}

// ============================================================================
// Kernel 3: out = X @ Wq_eff[b]^T (bf16x3). A tiles cp.async'd directly from
// g_xbf (pre-converted by K1) into double-buffered XT — no raw staging/cvt.
// smem: Whi 32K | Wlo 32K | XT[2] 2x64K = 192 KB.
// XT buffer layout: hi rows 0-127 (32K), lo at +32768.
// ============================================================================
#define K3S_W_HI 0
#define K3S_W_LO 32768
#define K3S_XT   65536     // buf b at +b*65536
#define K3_SMEM  196608

__device__ __forceinline__ void cvt_w512(const float* __restrict__ src,
                                         char* hi_base, char* lo_base, int tid) {
    if (tid < 256) {
#pragma unroll
        for (int i = 0; i < 16; i++) {
            const int idx = tid + i * 256;
            const int row = idx >> 5;
            const int kb  = (idx & 31) << 3;
            const float4 x = *(const float4*)(src + idx * 4);
            __nv_bfloat162 h0 = __floats2bfloat162_rn(x.x, x.y);
            __nv_bfloat162 h1 = __floats2bfloat162_rn(x.z, x.w);
            float2 f0 = __bfloat1622float2(h0);
            float2 f1 = __bfloat1622float2(h1);
            __nv_bfloat162 l0 = __floats2bfloat162_rn(x.x - f0.x, x.y - f0.y);
            __nv_bfloat162 l1 = __floats2bfloat162_rn(x.z - f1.x, x.w - f1.y);
            const unsigned off = sw_off(row, kb);
            *(__nv_bfloat162*)(hi_base + off)     = h0;
            *(__nv_bfloat162*)(hi_base + off + 4) = h1;
            *(__nv_bfloat162*)(lo_base + off)     = l0;
            *(__nv_bfloat162*)(lo_base + off + 4) = l1;
        }
    }
}

// cp.async one 128-pt chunk (= 64-pt blocks 2j, 2j+1) from g_xbf into XT buf.
// XT regions: [hi rows0-63][hi rows64-127][lo rows0-63][lo rows64-127], 16K ea.
__device__ __forceinline__ void k3_load_xbf(int chunk, char* dstXT, int tid) {
    const char* b0 = g_xbf + (size_t)(2 * chunk) * 32768;
    const char* b1 = b0 + 32768;
#pragma unroll
    for (int i = 0; i < 8; i++) {
        const int u = tid + i * 512;           // 0..4095 16B units
        const int r = u >> 10;                 // region 0..3
        const int w = (u & 1023) << 4;
        const char* src = ((r & 1) ? b1 : b0) + ((r >> 1) << 14) + w;
        cp16(dstXT + (r << 14) + w, src);
    }
}

__global__ void __launch_bounds__(512, 1)
k3_out_mma(float* __restrict__ out)
{
    extern __shared__ char smem[];
    const int tid  = threadIdx.x;
    const int lane = tid & 31;
    const int warp = tid >> 5;

    const unsigned xt_u = (unsigned)__cvta_generic_to_shared(smem + K3S_XT);
    const unsigned wh_u = (unsigned)__cvta_generic_to_shared(smem + K3S_W_HI);

    const int m0 = (warp & 3) * 32;
    const int n0 = (warp >> 2) * 32;
    const int qr = lane >> 2;
    const int qc = lane & 3;

    const int laneK = lane & 16;
    const int bKoff = (lane & 8) << 1;
    unsigned aBase[2], aSw[2], bBase[2], bSw[2];
#pragma unroll
    for (int mi = 0; mi < 2; mi++) {
        const int row = m0 + mi * 16 + (lane & 15);
        aSw[mi] = (unsigned)((row & 7) << 4);
        aBase[mi] = xt_u + row * 256;
    }
#pragma unroll
    for (int p = 0; p < 2; p++) {
        const int row = n0 + p * 16 + ((lane >> 1) & 8) + (lane & 7);
        bSw[p] = (unsigned)((row & 7) << 4);
        bBase[p] = wh_u + row * 256;
    }

    // Prolog: issue G0 (chunk0 -> XT[0]) and G1 (chunk1 -> XT[1]); cvt W(b=0)
    const int chunk0 = blockIdx.x;
    k3_load_xbf(chunk0, smem + K3S_XT, tid);
    cp_commit();
    if (chunk0 + NPART < NCHUNK3)
        k3_load_xbf(chunk0 + NPART, smem + K3S_XT + 65536, tid);
    cp_commit();
    cvt_w512(g_wqeff, smem + K3S_W_HI, smem + K3S_W_LO, tid);

    int cur_b = 0;
    int it = 0;
    for (int chunk = chunk0; chunk < NCHUNK3; chunk += NPART, it++) {
        const int cur = it & 1;
        const int b = chunk >> 9;

        cp_wait1();          // all groups except the newest done -> XT[cur] ready
        __syncthreads();     // visibility + all MMA(i-1) reads finished

        if (b != cur_b) {
            cvt_w512(g_wqeff + b * 16384, smem + K3S_W_HI, smem + K3S_W_LO, tid);
            cur_b = b;
            __syncthreads();
        }

        // ---- MMA(i) on XT[cur] ----
        float c[2][4][4];
#pragma unroll
        for (int mi = 0; mi < 2; mi++)
#pragma unroll
            for (int nj = 0; nj < 4; nj++)
#pragma unroll
                for (int z = 0; z < 4; z++) c[mi][nj][z] = 0.f;

        const unsigned bufo = (unsigned)(cur * 65536);
#pragma unroll
        for (int ks = 0; ks < 8; ks++) {
            const int kb = ks * 32;
            unsigned ah[2][4], al[2][4], bh[4][2], bl[4][2];
#pragma unroll
            for (int mi = 0; mi < 2; mi++) {
                const unsigned off = (unsigned)(kb + laneK) ^ aSw[mi];
                ldsm4(ah[mi], aBase[mi] + bufo + off);
                ldsm4(al[mi], aBase[mi] + bufo + 32768u + off);
            }
#pragma unroll
            for (int p = 0; p < 2; p++) {
                const unsigned off = (unsigned)(kb + bKoff) ^ bSw[p];
                unsigned t[4];
                ldsm4(t, bBase[p] + off);
                bh[2 * p][0] = t[0]; bh[2 * p][1] = t[1];
                bh[2 * p + 1][0] = t[2]; bh[2 * p + 1][1] = t[3];
                ldsm4(t, bBase[p] + 32768u + off);
                bl[2 * p][0] = t[0]; bl[2 * p][1] = t[1];
                bl[2 * p + 1][0] = t[2]; bl[2 * p + 1][1] = t[3];
            }
#pragma unroll
            for (int mi = 0; mi < 2; mi++)
#pragma unroll
                for (int nj = 0; nj < 4; nj++) {
                    mma_bf16(c[mi][nj], ah[mi][0], ah[mi][1], ah[mi][2], ah[mi][3],
                             bh[nj][0], bh[nj][1]);
                    mma_bf16(c[mi][nj], ah[mi][0], ah[mi][1], ah[mi][2], ah[mi][3],
                             bl[nj][0], bl[nj][1]);
                    mma_bf16(c[mi][nj], al[mi][0], al[mi][1], al[mi][2], al[mi][3],
                             bh[nj][0], bh[nj][1]);
                }
        }

        float* obase = out + (size_t)chunk * 16384;
#pragma unroll
        for (int mi = 0; mi < 2; mi++) {
            const int r = m0 + mi * 16 + qr;
#pragma unroll
            for (int nj = 0; nj < 4; nj++) {
                const int col = n0 + nj * 8 + qc * 2;
                *(float2*)(obase + r * 128 + col) =
                    make_float2(c[mi][nj][0], c[mi][nj][1]);
                *(float2*)(obase + (r + 8) * 128 + col) =
                    make_float2(c[mi][nj][2], c[mi][nj][3]);
            }
        }

        __syncthreads();     // all reads of XT[cur] done -> safe to refill
        const int nxt2 = chunk + 2 * NPART;
        if (nxt2 < NCHUNK3)
            k3_load_xbf(nxt2, smem + K3S_XT + cur * 65536, tid);
        cp_commit();         // unconditional: keeps group bookkeeping uniform
    }
}

// ============================================================================
extern "C" void kernel_launch(void* const* d_in, const int* in_sizes, int n_in,
                              void* d_out, int out_size)
{
    (void)in_sizes; (void)n_in; (void)out_size;
    const float* X     = (const float*)d_in[0];
    const float* Wq    = (const float*)d_in[1];
    const float* Wk    = (const float*)d_in[2];
    const float* Wv    = (const float*)d_in[3];
    const float* gamma = (const float*)d_in[4];
    const float* beta  = (const float*)d_in[5];
    float* out = (float*)d_out;

    cudaFuncSetAttribute(k1_kv_mma, cudaFuncAttributeMaxDynamicSharedMemorySize,
                         K1_SMEM);    // 226 KB
    cudaFuncSetAttribute(k3_out_mma, cudaFuncAttributeMaxDynamicSharedMemorySize,
                         K3_SMEM);    // 192 KB

    k1_kv_mma<<<NPART, 512, K1_SMEM>>>(X, Wk, Wv, gamma, beta);
    k2a_reduce<<<64, 256>>>();
    k2b_fold<<<256, 256>>>(Wq);
    k3_out_mma<<<NPART, 512, K3_SMEM>>>(out);
}

// round 16
// speedup vs baseline: 1.0770x; 1.0770x over previous
#include <cuda_runtime.h>
#include <cuda_bf16.h>
#include <cuda_fp16.h>

// Problem constants
#define NPART    148     // persistent CTAs (one per SM)
#define NCHUNK1  4096    // K1: chunks of 64 points  (262144/64);  b = chunk>>10
#define NCHUNK3  2048    // K3: chunks of 128 points (262144/128); b = chunk>>9

// Deterministic scratch (no cudaMalloc allowed)
__device__ float g_part[4 * NPART * 4096];   // per-CTA partial kv  [b][cta][h*1024+d*32+e]
__device__ float g_kv[4 * 4096];             // reduced kv          [b][h*1024+d*32+e]
__device__ float g_wqeff[4 * 16384];         // folded weights x65536 [b][n*128 + c]

// ---- cp.async helpers ----
__device__ __forceinline__ void cp16(void* smem_dst, const void* gsrc) {
    unsigned s = (unsigned)__cvta_generic_to_shared(smem_dst);
    asm volatile("cp.async.cg.shared.global [%0], [%1], 16;" :: "r"(s), "l"(gsrc));
}
__device__ __forceinline__ void cp_commit() {
    asm volatile("cp.async.commit_group;");
}
__device__ __forceinline__ void cp_wait_all() {
    asm volatile("cp.async.wait_group 0;");
}

// ---- shared mma infrastructure ----
// 16-bit tile [rows][256 bytes], XOR-swizzled at 16B granularity.
__device__ __forceinline__ unsigned sw_off(int row, int kbyte) {
    return (unsigned)((row << 8) + (kbyte ^ ((row & 7) << 4)));
}
// bf16 kn/vn tile [64 rows][512 bytes], XOR-swizzled at 16B granularity.
__device__ __forceinline__ unsigned skvb_off(int row, int chb) {
    return (unsigned)((row << 9) + (chb ^ ((row & 7) << 4)));
}

__device__ __forceinline__ void mma_bf16(float* c,
                                         unsigned a0, unsigned a1, unsigned a2, unsigned a3,
                                         unsigned b0, unsigned b1) {
    asm volatile(
        "mma.sync.aligned.m16n8k16.row.col.f32.bf16.bf16.f32 "
        "{%0,%1,%2,%3}, {%4,%5,%6,%7}, {%8,%9}, {%0,%1,%2,%3};"
        : "+f"(c[0]), "+f"(c[1]), "+f"(c[2]), "+f"(c[3])
        : "r"(a0), "r"(a1), "r"(a2), "r"(a3), "r"(b0), "r"(b1));
}

__device__ __forceinline__ void mma_f16(float* c,
                                        unsigned a0, unsigned a1, unsigned a2, unsigned a3,
                                        unsigned b0, unsigned b1) {
    asm volatile(
        "mma.sync.aligned.m16n8k16.row.col.f32.f16.f16.f32 "
        "{%0,%1,%2,%3}, {%4,%5,%6,%7}, {%8,%9}, {%0,%1,%2,%3};"
        : "+f"(c[0]), "+f"(c[1]), "+f"(c[2]), "+f"(c[3])
        : "r"(a0), "r"(a1), "r"(a2), "r"(a3), "r"(b0), "r"(b1));
}

__device__ __forceinline__ void ldsm4(unsigned* r, unsigned a) {
    asm volatile("ldmatrix.sync.aligned.m8n8.x4.shared.b16 {%0,%1,%2,%3}, [%4];"
                 : "=r"(r[0]), "=r"(r[1]), "=r"(r[2]), "=r"(r[3]) : "r"(a));
}
__device__ __forceinline__ void ldsm4t(unsigned* r, unsigned a) {
    asm volatile("ldmatrix.sync.aligned.m8n8.x4.trans.shared.b16 {%0,%1,%2,%3}, [%4];"
                 : "=r"(r[0]), "=r"(r[1]), "=r"(r[2]), "=r"(r[3]) : "r"(a));
}

__device__ __forceinline__ unsigned h2u(__half2 v) {
    return *reinterpret_cast<unsigned*>(&v);
}

// ============================================================================
// Kernel 1 (r14 balanced — best known): ALL 16 warps do proj MMA (16x64,
// bf16x3) + 16x16 tensor outer slice + shared LN/store/X-staging.
// smem: WT 128K | XT 32K | KVH 32K | KVL 32K | partk 1K | partv 1K = 226 KB
// ============================================================================
#define K1_WT_HI  0
#define K1_WT_LO  65536
#define K1_XT     131072
#define K1_KVH    163840
#define K1_KVL    196608
#define K1_PARTK  229376
#define K1_PARTV  230400
#define K1_SMEM   231424

__global__ void __launch_bounds__(512, 1)
k1_kv_mma(const float* __restrict__ X,
          const float* __restrict__ Wk, const float* __restrict__ Wv,
          const float* __restrict__ gamma, const float* __restrict__ beta)
{
    extern __shared__ char smem[];
    char* wth = smem + K1_WT_HI;
    char* wtl = smem + K1_WT_LO;
    char* xt  = smem + K1_XT;
    char* kvh = smem + K1_KVH;
    char* kvl = smem + K1_KVL;
    float2* partk = (float2*)(smem + K1_PARTK);
    float2* partv = (float2*)(smem + K1_PARTV);

    const unsigned xt_u  = (unsigned)__cvta_generic_to_shared(xt);
    const unsigned wth_u = (unsigned)__cvta_generic_to_shared(wth);
    const unsigned kvh_u = (unsigned)__cvta_generic_to_shared(kvh);

    const int tid  = threadIdx.x;
    const int lane = tid & 31;
    const int warp = tid >> 5;
    const int qr = lane >> 2;
    const int qc = lane & 3;

    // ---- One-time: transpose + bf16-split Wk|Wv into WT tiles ----
    for (int idx = tid; idx < 4096; idx += 512) {
        const int c  = idx >> 5;
        const int n4 = (idx & 31) << 2;
        const float4 wk = ((const float4*)Wk)[idx];
        const float4 wv = ((const float4*)Wv)[idx];
#pragma unroll
        for (int j = 0; j < 4; j++) {
            const float vk = (&wk.x)[j];
            const float vv = (&wv.x)[j];
            __nv_bfloat16 hk = __float2bfloat16(vk);
            __nv_bfloat16 hv = __float2bfloat16(vv);
            __nv_bfloat16 lk = __float2bfloat16(vk - __bfloat162float(hk));
            __nv_bfloat16 lv = __float2bfloat16(vv - __bfloat162float(hv));
            const unsigned ok = sw_off(n4 + j,       c * 2);
            const unsigned ov = sw_off(128 + n4 + j, c * 2);
            *(__nv_bfloat16*)(wth + ok) = hk;
            *(__nv_bfloat16*)(wtl + ok) = lk;
            *(__nv_bfloat16*)(wth + ov) = hv;
            *(__nv_bfloat16*)(wtl + ov) = lv;
        }
    }

    // ---- proj tile: 16 rows x 64 cols over the 64 x 256 (k|v) output ----
    const int m0  = (warp & 3) * 16;
    const int n0g = (warp >> 2) * 64;
    const int kw  = (n0g < 128);
    const int cg  = (warp >> 2) & 1;

    float gv[8], bv[8], gv1[8], bv1[8];
#pragma unroll
    for (int nj = 0; nj < 8; nj++) {
        const int ch = (n0g + nj * 8 + qc * 2) & 127;
        gv[nj] = gamma[ch];  bv[nj] = beta[ch];
        gv1[nj] = gamma[(ch + 1) & 127]; bv1[nj] = beta[(ch + 1) & 127];
    }

    const int laneK = lane & 16;
    const int bKoff = (lane & 8) << 1;
    unsigned aBase, aSw, bBase[4], bSw[4];
    {
        const int row = m0 + (lane & 15);
        aSw = (unsigned)((row & 7) << 4);
        aBase = xt_u + row * 256;
    }
#pragma unroll
    for (int p = 0; p < 4; p++) {
        const int row = n0g + p * 16 + ((lane >> 1) & 8) + (lane & 7);
        bSw[p] = (unsigned)((row & 7) << 4);
        bBase[p] = wth_u + row * 256;
    }

    // ---- outer slice: head hh2, d-half dh, e-half eh (16x16 kv tile) ----
    const int hh2 = warp >> 2;
    const int dh  = (warp >> 1) & 1;
    const int eh  = warp & 1;
    const int rkA = (lane & 7) + ((lane >> 4) & 1) * 8;
    const unsigned chbA = (unsigned)(hh2 * 64 + dh * 32 + ((lane >> 3) & 1) * 16);
    const unsigned aOut = kvh_u + rkA * 512 + (chbA ^ ((unsigned)(rkA & 7) << 4));
    const int rkB = (lane & 7) + ((lane >> 3) & 1) * 8;
    const unsigned swB = (unsigned)(rkB & 7) << 4;
    const unsigned chbB = (unsigned)(256 + hh2 * 64 + eh * 32 + ((lane >> 4) & 1) * 16);
    const unsigned bOut = kvh_u + rkB * 512 + (chbB ^ swB);

    float co[2][4];
#pragma unroll
    for (int nt = 0; nt < 2; nt++)
#pragma unroll
        for (int z = 0; z < 4; z++) co[nt][z] = 0.f;

    // ---- X staging ----
    float4 xr[4];
    const int chunk0 = blockIdx.x;
    {
        const float4* src = (const float4*)X + (size_t)chunk0 * 2048;
#pragma unroll
        for (int i = 0; i < 4; i++) xr[i] = src[tid + i * 512];
#pragma unroll
        for (int i = 0; i < 4; i++) {
            const int idx = tid + i * 512;
            const int row = idx >> 5;
            const int kb  = (idx & 31) << 3;
            const float4 x = xr[i];
            __nv_bfloat162 h0 = __floats2bfloat162_rn(x.x, x.y);
            __nv_bfloat162 h1 = __floats2bfloat162_rn(x.z, x.w);
            float2 f0 = __bfloat1622float2(h0);
            float2 f1 = __bfloat1622float2(h1);
            __nv_bfloat162 l0 = __floats2bfloat162_rn(x.x - f0.x, x.y - f0.y);
            __nv_bfloat162 l1 = __floats2bfloat162_rn(x.z - f1.x, x.w - f1.y);
            const unsigned off = sw_off(row, kb);
            *(__nv_bfloat162*)(xt + off)             = h0;
            *(__nv_bfloat162*)(xt + off + 4)         = h1;
            *(__nv_bfloat162*)(xt + 16384 + off)     = l0;
            *(__nv_bfloat162*)(xt + 16384 + off + 4) = l1;
        }
        const int c1 = chunk0 + NPART;
        if (c1 < NCHUNK1) {
            const float4* s1 = (const float4*)X + (size_t)c1 * 2048;
#pragma unroll
            for (int i = 0; i < 4; i++) xr[i] = s1[tid + i * 512];
        }
    }
    __syncthreads();

    int pend = -1, ob = -1;
    float c[8][4];

    for (int chunk = chunk0; chunk < NCHUNK1; chunk += NPART) {
        // ============ PHASE A: outer(i-1) + proj MMA(i) + LN partials ========
        if (pend >= 0) {
            const int bj = pend >> 10;
            if (bj != ob) {
                if (ob >= 0) {
                    float* dst = g_part + ((size_t)ob * NPART + blockIdx.x) * 4096
                               + hh2 * 1024 + (dh * 16 + qr) * 32 + eh * 16 + qc * 2;
#pragma unroll
                    for (int nt = 0; nt < 2; nt++) {
                        *(float2*)(dst + nt * 8)          = make_float2(co[nt][0], co[nt][1]);
                        *(float2*)(dst + 8 * 32 + nt * 8) = make_float2(co[nt][2], co[nt][3]);
#pragma unroll
                        for (int z = 0; z < 4; z++) co[nt][z] = 0.f;
                    }
                }
                ob = bj;
            }
#pragma unroll
            for (int ks = 0; ks < 4; ks++) {
                const unsigned off = (unsigned)(ks * 8192);
                unsigned Ah[4], Al[4], Bh[4], Bl[4];
                ldsm4t(Ah, aOut + off);
                ldsm4t(Al, aOut + 32768u + off);
                ldsm4t(Bh, bOut + off);
                ldsm4t(Bl, bOut + 32768u + off);
                mma_bf16(co[0], Ah[0], Ah[1], Ah[2], Ah[3], Bh[0], Bh[1]);
                mma_bf16(co[0], Ah[0], Ah[1], Ah[2], Ah[3], Bl[0], Bl[1]);
                mma_bf16(co[0], Al[0], Al[1], Al[2], Al[3], Bh[0], Bh[1]);
                mma_bf16(co[1], Ah[0], Ah[1], Ah[2], Ah[3], Bh[2], Bh[3]);
                mma_bf16(co[1], Ah[0], Ah[1], Ah[2], Ah[3], Bl[2], Bl[3]);
                mma_bf16(co[1], Al[0], Al[1], Al[2], Al[3], Bh[2], Bh[3]);
            }
        }

        // ---- proj MMA (bf16x3), 16x64 tile ----
#pragma unroll
        for (int nj = 0; nj < 8; nj++)
#pragma unroll
            for (int z = 0; z < 4; z++) c[nj][z] = 0.f;

#pragma unroll
        for (int ks = 0; ks < 8; ks++) {
            const int kb = ks * 32;
            unsigned ah[4], al[4];
            {
                const unsigned off = (unsigned)(kb + laneK) ^ aSw;
                ldsm4(ah, aBase + off);
                ldsm4(al, aBase + 16384u + off);
            }
#pragma unroll
            for (int p = 0; p < 4; p++) {
                const unsigned off = (unsigned)(kb + bKoff) ^ bSw[p];
                unsigned th[4], tl[4];
                ldsm4(th, bBase[p] + off);
                ldsm4(tl, bBase[p] + 65536u + off);
                float* c0 = c[2 * p];
                float* c1 = c[2 * p + 1];
                mma_bf16(c0, ah[0], ah[1], ah[2], ah[3], th[0], th[1]);
                mma_bf16(c0, ah[0], ah[1], ah[2], ah[3], tl[0], tl[1]);
                mma_bf16(c0, al[0], al[1], al[2], al[3], th[0], th[1]);
                mma_bf16(c1, ah[0], ah[1], ah[2], ah[3], th[2], th[3]);
                mma_bf16(c1, ah[0], ah[1], ah[2], ah[3], tl[2], tl[3]);
                mma_bf16(c1, al[0], al[1], al[2], al[3], th[2], th[3]);
            }
        }

        // ---- LN partial stats ----
#pragma unroll
        for (int half = 0; half < 2; half++) {
            float s = 0.f, q = 0.f;
#pragma unroll
            for (int nj = 0; nj < 8; nj++) {
                const float v0 = c[nj][half * 2];
                const float v1 = c[nj][half * 2 + 1];
                s += v0 + v1;
                q += v0 * v0 + v1 * v1;
            }
            s += __shfl_xor_sync(0xffffffffu, s, 1);
            q += __shfl_xor_sync(0xffffffffu, q, 1);
            s += __shfl_xor_sync(0xffffffffu, s, 2);
            q += __shfl_xor_sync(0xffffffffu, q, 2);
            if (qc == 0) {
                const int row = m0 + half * 8 + qr;
                (kw ? partk : partv)[row * 2 + cg] = make_float2(s, q);
            }
        }
        __syncthreads();   // bar1

        // ============ PHASE B: normalize + store + X staging ================
        {
            const float2* pk = kw ? partk : partv;
#pragma unroll
            for (int half = 0; half < 2; half++) {
                const int row = m0 + half * 8 + qr;
                const float2 p0 = pk[row * 2];
                const float2 p1 = pk[row * 2 + 1];
                const float mu = (p0.x + p1.x) * (1.f / 128.f);
                const float ms = (p0.y + p1.y) * (1.f / 128.f);
                const float rr = rsqrtf(ms - mu * mu + 1e-5f);
                const float mm = -mu * rr;
#pragma unroll
                for (int nj = 0; nj < 8; nj++) {
                    float& v0 = c[nj][half * 2];
                    float& v1 = c[nj][half * 2 + 1];
                    v0 = fmaf(fmaf(v0, rr, mm), gv[nj], bv[nj]);
                    v1 = fmaf(fmaf(v1, rr, mm), gv1[nj], bv1[nj]);
                }
            }
#pragma unroll
            for (int nj = 0; nj < 8; nj++) {
                const int chb = (n0g + nj * 8 + qc * 2) * 2;
                __nv_bfloat162 h0 = __floats2bfloat162_rn(c[nj][0], c[nj][1]);
                float2 hf0 = __bfloat1622float2(h0);
                __nv_bfloat162 l0 = __floats2bfloat162_rn(c[nj][0] - hf0.x,
                                                          c[nj][1] - hf0.y);
                __nv_bfloat162 h1 = __floats2bfloat162_rn(c[nj][2], c[nj][3]);
                float2 hf1 = __bfloat1622float2(h1);
                __nv_bfloat162 l1 = __floats2bfloat162_rn(c[nj][2] - hf1.x,
                                                          c[nj][3] - hf1.y);
                const unsigned o0 = skvb_off(m0 + qr,     chb);
                const unsigned o1 = skvb_off(m0 + 8 + qr, chb);
                *(__nv_bfloat162*)(kvh + o0) = h0;
                *(__nv_bfloat162*)(kvl + o0) = l0;
                *(__nv_bfloat162*)(kvh + o1) = h1;
                *(__nv_bfloat162*)(kvl + o1) = l1;
            }
        }
        // cvt X(i+1) regs -> XT; prefetch X(i+2)
        {
            const int nxt = chunk + NPART;
            if (nxt < NCHUNK1) {
#pragma unroll
                for (int i = 0; i < 4; i++) {
                    const int idx = tid + i * 512;
                    const int row = idx >> 5;
                    const int kb  = (idx & 31) << 3;
                    const float4 x = xr[i];
                    __nv_bfloat162 h0 = __floats2bfloat162_rn(x.x, x.y);
                    __nv_bfloat162 h1 = __floats2bfloat162_rn(x.z, x.w);
                    float2 f0 = __bfloat1622float2(h0);
                    float2 f1 = __bfloat1622float2(h1);
                    __nv_bfloat162 l0 = __floats2bfloat162_rn(x.x - f0.x, x.y - f0.y);
                    __nv_bfloat162 l1 = __floats2bfloat162_rn(x.z - f1.x, x.w - f1.y);
                    const unsigned off = sw_off(row, kb);
                    *(__nv_bfloat162*)(xt + off)             = h0;
                    *(__nv_bfloat162*)(xt + off + 4)         = h1;
                    *(__nv_bfloat162*)(xt + 16384 + off)     = l0;
                    *(__nv_bfloat162*)(xt + 16384 + off + 4) = l1;
                }
                const int nxt2 = nxt + NPART;
                if (nxt2 < NCHUNK1) {
                    const float4* src = (const float4*)X + (size_t)nxt2 * 2048;
#pragma unroll
                    for (int i = 0; i < 4; i++) xr[i] = src[tid + i * 512];
                }
            }
        }
        pend = chunk;
        __syncthreads();   // bar2
    }

    // Epilogue: outer for the final chunk, then flush
    if (pend >= 0) {
        const int bj = pend >> 10;
        if (bj != ob) {
            if (ob >= 0) {
                float* dst = g_part + ((size_t)ob * NPART + blockIdx.x) * 4096
                           + hh2 * 1024 + (dh * 16 + qr) * 32 + eh * 16 + qc * 2;
#pragma unroll
                for (int nt = 0; nt < 2; nt++) {
                    *(float2*)(dst + nt * 8)          = make_float2(co[nt][0], co[nt][1]);
                    *(float2*)(dst + 8 * 32 + nt * 8) = make_float2(co[nt][2], co[nt][3]);
#pragma unroll
                    for (int z = 0; z < 4; z++) co[nt][z] = 0.f;
                }
            }
            ob = bj;
        }
#pragma unroll
        for (int ks = 0; ks < 4; ks++) {
            const unsigned off = (unsigned)(ks * 8192);
            unsigned Ah[4], Al[4], Bh[4], Bl[4];
            ldsm4t(Ah, aOut + off);
            ldsm4t(Al, aOut + 32768u + off);
            ldsm4t(Bh, bOut + off);
            ldsm4t(Bl, bOut + 32768u + off);
            mma_bf16(co[0], Ah[0], Ah[1], Ah[2], Ah[3], Bh[0], Bh[1]);
            mma_bf16(co[0], Ah[0], Ah[1], Ah[2], Ah[3], Bl[0], Bl[1]);
            mma_bf16(co[0], Al[0], Al[1], Al[2], Al[3], Bh[0], Bh[1]);
            mma_bf16(co[1], Ah[0], Ah[1], Ah[2], Ah[3], Bh[2], Bh[3]);
            mma_bf16(co[1], Ah[0], Ah[1], Ah[2], Ah[3], Bl[2], Bl[3]);
            mma_bf16(co[1], Al[0], Al[1], Al[2], Al[3], Bh[2], Bh[3]);
        }
        float* dst = g_part + ((size_t)ob * NPART + blockIdx.x) * 4096
                   + hh2 * 1024 + (dh * 16 + qr) * 32 + eh * 16 + qc * 2;
#pragma unroll
        for (int nt = 0; nt < 2; nt++) {
            *(float2*)(dst + nt * 8)          = make_float2(co[nt][0], co[nt][1]);
            *(float2*)(dst + 8 * 32 + nt * 8) = make_float2(co[nt][2], co[nt][3]);
        }
    }
}

// ============================================================================
// Kernel 2a: reduce 148 per-CTA partials -> g_kv.
// ============================================================================
__global__ void k2a_reduce()
{
    const int gid = blockIdx.x * 256 + threadIdx.x;
    const int b = gid >> 12;
    const int e = gid & 4095;
    const float* src = g_part + (size_t)b * NPART * 4096 + e;
    float s = 0.f;
#pragma unroll 4
    for (int j = 0; j < NPART; j++) s += src[(size_t)j * 4096];
    g_kv[gid] = s;
}

// ============================================================================
// Kernel 2b: Wq_eff_scaled[b][n][c] = sum_d Wq[c][h*32+d] * kv[b][h][d][e]
// (scaled by 65536 relative to the true folded weight; K3 divides at store)
// ============================================================================
__global__ void k2b_fold(const float* __restrict__ Wq)
{
    const int gid = blockIdx.x * 256 + threadIdx.x;
    const int b  = gid >> 14;
    const int r  = gid & 16383;
    const int cp = r >> 7;
    const int co = r & 127;
    const int e  = co >> 2;
    const int h  = co & 3;
    const float* wq = Wq + cp * 128 + h * 32;
    const float* kv = g_kv + b * 4096 + h * 1024 + e;
    float s = 0.f;
#pragma unroll
    for (int d = 0; d < 32; d++) s += wq[d] * kv[d * 32];
    g_wqeff[b * 16384 + co * 128 + cp] = s;
}

// ============================================================================
// Kernel 3 (fp16x2): out = (Xh + Xl) @ Ws^T / 65536, fp32 accumulate.
// Ws = Wq_eff*65536 in single fp16; X split into fp16 hi+lo (X exact to 2^-22).
// 2 MMA products per tile (was 3), B-lo loads eliminated.
// smem: Ws 32K | (unused 32K) | Xhi 32K | Xlo 32K | raw 64K = 192 KB
// ============================================================================
#define K3S_W_HI 0
#define K3S_X_HI 65536
#define K3S_X_LO 98304
#define K3S_RAW  131072
#define K3_SMEM  196608
#define K3_OSCALE (1.f / 65536.f)

__device__ __forceinline__ void cvt_tile512_h(const float* __restrict__ src,
                                              char* hi_base, char* lo_base, int tid) {
#pragma unroll
    for (int i = 0; i < 8; i++) {
        const int idx = tid + i * 512;
        const int row = idx >> 5;
        const int kb  = (idx & 31) << 3;
        const float4 x = *(const float4*)(src + idx * 4);
        __half2 h0 = __floats2half2_rn(x.x, x.y);
        __half2 h1 = __floats2half2_rn(x.z, x.w);
        float2 f0 = __half22float2(h0);
        float2 f1 = __half22float2(h1);
        __half2 l0 = __floats2half2_rn(x.x - f0.x, x.y - f0.y);
        __half2 l1 = __floats2half2_rn(x.z - f1.x, x.w - f1.y);
        const unsigned off = sw_off(row, kb);
        *(__half2*)(hi_base + off)     = h0;
        *(__half2*)(hi_base + off + 4) = h1;
        *(__half2*)(lo_base + off)     = l0;
        *(__half2*)(lo_base + off + 4) = l1;
    }
}

__device__ __forceinline__ void cvt_w512_h(const float* __restrict__ src,
                                           char* w_base, int tid) {
    if (tid < 256) {
#pragma unroll
        for (int i = 0; i < 16; i++) {
            const int idx = tid + i * 256;
            const int row = idx >> 5;
            const int kb  = (idx & 31) << 3;
            const float4 x = *(const float4*)(src + idx * 4);
            __half2 h0 = __floats2half2_rn(x.x, x.y);
            __half2 h1 = __floats2half2_rn(x.z, x.w);
            const unsigned off = sw_off(row, kb);
            *(__half2*)(w_base + off)     = h0;
            *(__half2*)(w_base + off + 4) = h1;
        }
    }
}

__global__ void __launch_bounds__(512, 1)
k3_out_mma(const float* __restrict__ X, float* __restrict__ out)
{
    extern __shared__ char smem[];
    const int tid  = threadIdx.x;
    const int lane = tid & 31;
    const int warp = tid >> 5;

    const int m0 = (warp & 3) * 32;
    const int n0 = (warp >> 2) * 32;
    const int qr = lane >> 2;
    const int qc = lane & 3;

    float* raw = (float*)(smem + K3S_RAW);

    const unsigned xh_u = (unsigned)__cvta_generic_to_shared(smem + K3S_X_HI);
    const unsigned wh_u = (unsigned)__cvta_generic_to_shared(smem + K3S_W_HI);

    const int laneK = lane & 16;
    const int bKoff = (lane & 8) << 1;
    unsigned aBase[2], aSw[2], bBase[2], bSw[2];
#pragma unroll
    for (int mi = 0; mi < 2; mi++) {
        const int row = m0 + mi * 16 + (lane & 15);
        aSw[mi] = (unsigned)((row & 7) << 4);
        aBase[mi] = xh_u + row * 256;
    }
#pragma unroll
    for (int p = 0; p < 2; p++) {
        const int row = n0 + p * 16 + ((lane >> 1) & 8) + (lane & 7);
        bSw[p] = (unsigned)((row & 7) << 4);
        bBase[p] = wh_u + row * 256;
    }

    {
        const float* src = X + (size_t)blockIdx.x * 16384;
#pragma unroll
        for (int i = 0; i < 8; i++)
            cp16(raw + (tid + i * 512) * 4, src + (tid + i * 512) * 4);
        cp_commit();
    }

    int cur_b = -1;
    for (int chunk = blockIdx.x; chunk < NCHUNK3; chunk += NPART) {
        const int b = chunk >> 9;

        cp_wait_all();
        __syncthreads();

        if (b != cur_b) {
            cvt_w512_h(g_wqeff + b * 16384, smem + K3S_W_HI, tid);
            cur_b = b;
        }
        cvt_tile512_h(raw, smem + K3S_X_HI, smem + K3S_X_LO, tid);
        __syncthreads();

        {
            const int nxt = chunk + NPART;
            if (nxt < NCHUNK3) {
                const float* src = X + (size_t)nxt * 16384;
#pragma unroll
                for (int i = 0; i < 8; i++)
                    cp16(raw + (tid + i * 512) * 4, src + (tid + i * 512) * 4);
                cp_commit();
            }
        }

        float c[2][4][4];
#pragma unroll
        for (int mi = 0; mi < 2; mi++)
#pragma unroll
            for (int nj = 0; nj < 4; nj++)
#pragma unroll
                for (int z = 0; z < 4; z++) c[mi][nj][z] = 0.f;

#pragma unroll
        for (int ks = 0; ks < 8; ks++) {
            const int kb = ks * 32;
            unsigned ah[2][4], al[2][4], bh[4][2];
#pragma unroll
            for (int mi = 0; mi < 2; mi++) {
                const unsigned off = (unsigned)(kb + laneK) ^ aSw[mi];
                ldsm4(ah[mi], aBase[mi] + off);
                ldsm4(al[mi], aBase[mi] + 32768u + off);
            }
#pragma unroll
            for (int p = 0; p < 2; p++) {
                const unsigned off = (unsigned)(kb + bKoff) ^ bSw[p];
                unsigned t[4];
                ldsm4(t, bBase[p] + off);
                bh[2 * p][0] = t[0]; bh[2 * p][1] = t[1];
                bh[2 * p + 1][0] = t[2]; bh[2 * p + 1][1] = t[3];
            }
#pragma unroll
            for (int mi = 0; mi < 2; mi++)
#pragma unroll
                for (int nj = 0; nj < 4; nj++) {
                    mma_f16(c[mi][nj], ah[mi][0], ah[mi][1], ah[mi][2], ah[mi][3],
                            bh[nj][0], bh[nj][1]);
                    mma_f16(c[mi][nj], al[mi][0], al[mi][1], al[mi][2], al[mi][3],
                            bh[nj][0], bh[nj][1]);
                }
        }

        float* obase = out + (size_t)chunk * 16384;
#pragma unroll
        for (int mi = 0; mi < 2; mi++) {
            const int r = m0 + mi * 16 + qr;
#pragma unroll
            for (int nj = 0; nj < 4; nj++) {
                const int col = n0 + nj * 8 + qc * 2;
                *(float2*)(obase + r * 128 + col) =
                    make_float2(c[mi][nj][0] * K3_OSCALE, c[mi][nj][1] * K3_OSCALE);
                *(float2*)(obase + (r + 8) * 128 + col) =
                    make_float2(c[mi][nj][2] * K3_OSCALE, c[mi][nj][3] * K3_OSCALE);
            }
        }
    }
}

// ============================================================================
extern "C" void kernel_launch(void* const* d_in, const int* in_sizes, int n_in,
                              void* d_out, int out_size)
{
    (void)in_sizes; (void)n_in; (void)out_size;
    const float* X     = (const float*)d_in[0];
    const float* Wq    = (const float*)d_in[1];
    const float* Wk    = (const float*)d_in[2];
    const float* Wv    = (const float*)d_in[3];
    const float* gamma = (const float*)d_in[4];
    const float* beta  = (const float*)d_in[5];
    float* out = (float*)d_out;

    cudaFuncSetAttribute(k1_kv_mma, cudaFuncAttributeMaxDynamicSharedMemorySize,
                         K1_SMEM);    // 226 KB
    cudaFuncSetAttribute(k3_out_mma, cudaFuncAttributeMaxDynamicSharedMemorySize,
                         K3_SMEM);    // 192 KB

    k1_kv_mma<<<NPART, 512, K1_SMEM>>>(X, Wk, Wv, gamma, beta);
    k2a_reduce<<<64, 256>>>();
    k2b_fold<<<256, 256>>>(Wq);
    k3_out_mma<<<NPART, 512, K3_SMEM>>>(X, out);
}

// round 17
// speedup vs baseline: 1.3008x; 1.2079x over previous
#include <cuda_runtime.h>
#include <cuda_bf16.h>
#include <cuda_fp16.h>

// Problem constants
#define NPART    148     // persistent CTAs (one per SM)
#define NCHUNK1  4096    // K1: chunks of 64 points  (262144/64);  b = chunk>>10
#define NCHUNK3  2048    // K3: chunks of 128 points (262144/128); b = chunk>>9

// Deterministic scratch (no cudaMalloc allowed)
__device__ float g_part[4 * NPART * 4096];   // per-CTA partial kv  [b][cta][h*1024+d*32+e]
__device__ float g_kv[4 * 4096];             // reduced kv          [b][h*1024+d*32+e]
__device__ float g_wqeff[4 * 16384];         // folded weights x65536 [b][n*128 + c]

// ---- cp.async helpers ----
__device__ __forceinline__ void cp16(void* smem_dst, const void* gsrc) {
    unsigned s = (unsigned)__cvta_generic_to_shared(smem_dst);
    asm volatile("cp.async.cg.shared.global [%0], [%1], 16;" :: "r"(s), "l"(gsrc));
}
__device__ __forceinline__ void cp_commit() {
    asm volatile("cp.async.commit_group;");
}
__device__ __forceinline__ void cp_wait_all() {
    asm volatile("cp.async.wait_group 0;");
}

// ---- shared mma infrastructure ----
// 16-bit tile [rows][256 bytes], XOR-swizzled at 16B granularity.
__device__ __forceinline__ unsigned sw_off(int row, int kbyte) {
    return (unsigned)((row << 8) + (kbyte ^ ((row & 7) << 4)));
}
// bf16 kn/vn tile [64 rows][512 bytes], XOR-swizzled at 16B granularity.
__device__ __forceinline__ unsigned skvb_off(int row, int chb) {
    return (unsigned)((row << 9) + (chb ^ ((row & 7) << 4)));
}

__device__ __forceinline__ void mma_bf16(float* c,
                                         unsigned a0, unsigned a1, unsigned a2, unsigned a3,
                                         unsigned b0, unsigned b1) {
    asm volatile(
        "mma.sync.aligned.m16n8k16.row.col.f32.bf16.bf16.f32 "
        "{%0,%1,%2,%3}, {%4,%5,%6,%7}, {%8,%9}, {%0,%1,%2,%3};"
        : "+f"(c[0]), "+f"(c[1]), "+f"(c[2]), "+f"(c[3])
        : "r"(a0), "r"(a1), "r"(a2), "r"(a3), "r"(b0), "r"(b1));
}

__device__ __forceinline__ void mma_f16(float* c,
                                        unsigned a0, unsigned a1, unsigned a2, unsigned a3,
                                        unsigned b0, unsigned b1) {
    asm volatile(
        "mma.sync.aligned.m16n8k16.row.col.f32.f16.f16.f32 "
        "{%0,%1,%2,%3}, {%4,%5,%6,%7}, {%8,%9}, {%0,%1,%2,%3};"
        : "+f"(c[0]), "+f"(c[1]), "+f"(c[2]), "+f"(c[3])
        : "r"(a0), "r"(a1), "r"(a2), "r"(a3), "r"(b0), "r"(b1));
}

__device__ __forceinline__ void ldsm4(unsigned* r, unsigned a) {
    asm volatile("ldmatrix.sync.aligned.m8n8.x4.shared.b16 {%0,%1,%2,%3}, [%4];"
                 : "=r"(r[0]), "=r"(r[1]), "=r"(r[2]), "=r"(r[3]) : "r"(a));
}
__device__ __forceinline__ void ldsm4t(unsigned* r, unsigned a) {
    asm volatile("ldmatrix.sync.aligned.m8n8.x4.trans.shared.b16 {%0,%1,%2,%3}, [%4];"
                 : "=r"(r[0]), "=r"(r[1]), "=r"(r[2]), "=r"(r[3]) : "r"(a));
}

// ============================================================================
// Kernel 1 (fp16x2 projection): ALL 16 warps do proj MMA (16x64, fp16:
// X split hi/lo, W single fp16 scaled x4096) + 16x16 bf16x3 tensor outer
// slice + shared LN/store/X-staging. LN un-scales by 1/4096.
// smem: WT 64K | XT 32K | KVH 32K | KVL 32K | partk 1K | partv 1K = 162 KB
// ============================================================================
#define K1_WSCALE 4096.f
#define K1_WT     0          // 256 rows x 256B fp16 (64K)
#define K1_XT     65536      // hi 16K at +0, lo 16K at +16384
#define K1_KVH    98304      // [64 pt][256 ch] bf16 hi (32K)
#define K1_KVL    131072     // lo (32K)
#define K1_PARTK  163840
#define K1_PARTV  164864
#define K1_SMEM   165888

__global__ void __launch_bounds__(512, 1)
k1_kv_mma(const float* __restrict__ X,
          const float* __restrict__ Wk, const float* __restrict__ Wv,
          const float* __restrict__ gamma, const float* __restrict__ beta)
{
    extern __shared__ char smem[];
    char* wt  = smem + K1_WT;
    char* xt  = smem + K1_XT;
    char* kvh = smem + K1_KVH;
    char* kvl = smem + K1_KVL;
    float2* partk = (float2*)(smem + K1_PARTK);
    float2* partv = (float2*)(smem + K1_PARTV);

    const unsigned xt_u  = (unsigned)__cvta_generic_to_shared(xt);
    const unsigned wt_u  = (unsigned)__cvta_generic_to_shared(wt);
    const unsigned kvh_u = (unsigned)__cvta_generic_to_shared(kvh);

    const int tid  = threadIdx.x;
    const int lane = tid & 31;
    const int warp = tid >> 5;
    const int qr = lane >> 2;
    const int qc = lane & 3;

    // ---- One-time: transpose + fp16-scale Wk|Wv into WT tile (256 rows) ----
    for (int idx = tid; idx < 4096; idx += 512) {
        const int c  = idx >> 5;
        const int n4 = (idx & 31) << 2;
        const float4 wk = ((const float4*)Wk)[idx];
        const float4 wv = ((const float4*)Wv)[idx];
#pragma unroll
        for (int j = 0; j < 4; j++) {
            const unsigned ok = sw_off(n4 + j,       c * 2);
            const unsigned ov = sw_off(128 + n4 + j, c * 2);
            *(__half*)(wt + ok) = __float2half((&wk.x)[j] * K1_WSCALE);
            *(__half*)(wt + ov) = __float2half((&wv.x)[j] * K1_WSCALE);
        }
    }

    // ---- proj tile: 16 rows x 64 cols over the 64 x 256 (k|v) output ----
    const int m0  = (warp & 3) * 16;
    const int n0g = (warp >> 2) * 64;
    const int kw  = (n0g < 128);
    const int cg  = (warp >> 2) & 1;

    float gv[8], bv[8], gv1[8], bv1[8];
#pragma unroll
    for (int nj = 0; nj < 8; nj++) {
        const int ch = (n0g + nj * 8 + qc * 2) & 127;
        gv[nj] = gamma[ch];  bv[nj] = beta[ch];
        gv1[nj] = gamma[(ch + 1) & 127]; bv1[nj] = beta[(ch + 1) & 127];
    }

    const int laneK = lane & 16;
    const int bKoff = (lane & 8) << 1;
    unsigned aBase, aSw, bBase[4], bSw[4];
    {
        const int row = m0 + (lane & 15);
        aSw = (unsigned)((row & 7) << 4);
        aBase = xt_u + row * 256;
    }
#pragma unroll
    for (int p = 0; p < 4; p++) {
        const int row = n0g + p * 16 + ((lane >> 1) & 8) + (lane & 7);
        bSw[p] = (unsigned)((row & 7) << 4);
        bBase[p] = wt_u + row * 256;
    }

    // ---- outer slice: head hh2, d-half dh, e-half eh (16x16 kv tile) ----
    const int hh2 = warp >> 2;
    const int dh  = (warp >> 1) & 1;
    const int eh  = warp & 1;
    const int rkA = (lane & 7) + ((lane >> 4) & 1) * 8;
    const unsigned chbA = (unsigned)(hh2 * 64 + dh * 32 + ((lane >> 3) & 1) * 16);
    const unsigned aOut = kvh_u + rkA * 512 + (chbA ^ ((unsigned)(rkA & 7) << 4));
    const int rkB = (lane & 7) + ((lane >> 3) & 1) * 8;
    const unsigned swB = (unsigned)(rkB & 7) << 4;
    const unsigned chbB = (unsigned)(256 + hh2 * 64 + eh * 32 + ((lane >> 4) & 1) * 16);
    const unsigned bOut = kvh_u + rkB * 512 + (chbB ^ swB);

    float co[2][4];
#pragma unroll
    for (int nt = 0; nt < 2; nt++)
#pragma unroll
        for (int z = 0; z < 4; z++) co[nt][z] = 0.f;

    // ---- X staging (fp16 hi/lo) ----
    float4 xr[4];
    const int chunk0 = blockIdx.x;
    {
        const float4* src = (const float4*)X + (size_t)chunk0 * 2048;
#pragma unroll
        for (int i = 0; i < 4; i++) xr[i] = src[tid + i * 512];
#pragma unroll
        for (int i = 0; i < 4; i++) {
            const int idx = tid + i * 512;
            const int row = idx >> 5;
            const int kb  = (idx & 31) << 3;
            const float4 x = xr[i];
            __half2 h0 = __floats2half2_rn(x.x, x.y);
            __half2 h1 = __floats2half2_rn(x.z, x.w);
            float2 f0 = __half22float2(h0);
            float2 f1 = __half22float2(h1);
            __half2 l0 = __floats2half2_rn(x.x - f0.x, x.y - f0.y);
            __half2 l1 = __floats2half2_rn(x.z - f1.x, x.w - f1.y);
            const unsigned off = sw_off(row, kb);
            *(__half2*)(xt + off)             = h0;
            *(__half2*)(xt + off + 4)         = h1;
            *(__half2*)(xt + 16384 + off)     = l0;
            *(__half2*)(xt + 16384 + off + 4) = l1;
        }
        const int c1 = chunk0 + NPART;
        if (c1 < NCHUNK1) {
            const float4* s1 = (const float4*)X + (size_t)c1 * 2048;
#pragma unroll
            for (int i = 0; i < 4; i++) xr[i] = s1[tid + i * 512];
        }
    }
    __syncthreads();

    int pend = -1, ob = -1;
    float c[8][4];
    const float inv  = 1.f / (128.f * K1_WSCALE);
    const float inv2 = 1.f / (128.f * K1_WSCALE * K1_WSCALE);

    for (int chunk = chunk0; chunk < NCHUNK1; chunk += NPART) {
        // ============ PHASE A: outer(i-1) + proj MMA(i) + LN partials ========
        if (pend >= 0) {
            const int bj = pend >> 10;
            if (bj != ob) {
                if (ob >= 0) {
                    float* dst = g_part + ((size_t)ob * NPART + blockIdx.x) * 4096
                               + hh2 * 1024 + (dh * 16 + qr) * 32 + eh * 16 + qc * 2;
#pragma unroll
                    for (int nt = 0; nt < 2; nt++) {
                        *(float2*)(dst + nt * 8)          = make_float2(co[nt][0], co[nt][1]);
                        *(float2*)(dst + 8 * 32 + nt * 8) = make_float2(co[nt][2], co[nt][3]);
#pragma unroll
                        for (int z = 0; z < 4; z++) co[nt][z] = 0.f;
                    }
                }
                ob = bj;
            }
#pragma unroll
            for (int ks = 0; ks < 4; ks++) {
                const unsigned off = (unsigned)(ks * 8192);
                unsigned Ah[4], Al[4], Bh[4], Bl[4];
                ldsm4t(Ah, aOut + off);
                ldsm4t(Al, aOut + 32768u + off);
                ldsm4t(Bh, bOut + off);
                ldsm4t(Bl, bOut + 32768u + off);
                mma_bf16(co[0], Ah[0], Ah[1], Ah[2], Ah[3], Bh[0], Bh[1]);
                mma_bf16(co[0], Ah[0], Ah[1], Ah[2], Ah[3], Bl[0], Bl[1]);
                mma_bf16(co[0], Al[0], Al[1], Al[2], Al[3], Bh[0], Bh[1]);
                mma_bf16(co[1], Ah[0], Ah[1], Ah[2], Ah[3], Bh[2], Bh[3]);
                mma_bf16(co[1], Ah[0], Ah[1], Ah[2], Ah[3], Bl[2], Bl[3]);
                mma_bf16(co[1], Al[0], Al[1], Al[2], Al[3], Bh[2], Bh[3]);
            }
        }

        // ---- proj MMA (fp16x2), 16x64 tile ----
#pragma unroll
        for (int nj = 0; nj < 8; nj++)
#pragma unroll
            for (int z = 0; z < 4; z++) c[nj][z] = 0.f;

#pragma unroll
        for (int ks = 0; ks < 8; ks++) {
            const int kb = ks * 32;
            unsigned ah[4], al[4];
            {
                const unsigned off = (unsigned)(kb + laneK) ^ aSw;
                ldsm4(ah, aBase + off);
                ldsm4(al, aBase + 16384u + off);
            }
#pragma unroll
            for (int p = 0; p < 4; p++) {
                const unsigned off = (unsigned)(kb + bKoff) ^ bSw[p];
                unsigned th[4];
                ldsm4(th, bBase[p] + off);
                float* c0 = c[2 * p];
                float* c1 = c[2 * p + 1];
                mma_f16(c0, ah[0], ah[1], ah[2], ah[3], th[0], th[1]);
                mma_f16(c0, al[0], al[1], al[2], al[3], th[0], th[1]);
                mma_f16(c1, ah[0], ah[1], ah[2], ah[3], th[2], th[3]);
                mma_f16(c1, al[0], al[1], al[2], al[3], th[2], th[3]);
            }
        }

        // ---- LN partial stats (on 4096x-scaled values) ----
#pragma unroll
        for (int half = 0; half < 2; half++) {
            float s = 0.f, q = 0.f;
#pragma unroll
            for (int nj = 0; nj < 8; nj++) {
                const float v0 = c[nj][half * 2];
                const float v1 = c[nj][half * 2 + 1];
                s += v0 + v1;
                q += v0 * v0 + v1 * v1;
            }
            s += __shfl_xor_sync(0xffffffffu, s, 1);
            q += __shfl_xor_sync(0xffffffffu, q, 1);
            s += __shfl_xor_sync(0xffffffffu, s, 2);
            q += __shfl_xor_sync(0xffffffffu, q, 2);
            if (qc == 0) {
                const int row = m0 + half * 8 + qr;
                (kw ? partk : partv)[row * 2 + cg] = make_float2(s, q);
            }
        }
        __syncthreads();   // bar1

        // ============ PHASE B: normalize (un-scale) + store + X staging ======
        {
            const float2* pk = kw ? partk : partv;
#pragma unroll
            for (int half = 0; half < 2; half++) {
                const int row = m0 + half * 8 + qr;
                const float2 p0 = pk[row * 2];
                const float2 p1 = pk[row * 2 + 1];
                const float mu = (p0.x + p1.x) * inv;              // true mean
                const float ms = (p0.y + p1.y) * inv2;             // true E[x^2]
                const float rr = rsqrtf(ms - mu * mu + 1e-5f);
                const float rrs = rr * (1.f / K1_WSCALE);          // applies to scaled v
                const float mm = -mu * rr;
#pragma unroll
                for (int nj = 0; nj < 8; nj++) {
                    float& v0 = c[nj][half * 2];
                    float& v1 = c[nj][half * 2 + 1];
                    v0 = fmaf(fmaf(v0, rrs, mm), gv[nj], bv[nj]);
                    v1 = fmaf(fmaf(v1, rrs, mm), gv1[nj], bv1[nj]);
                }
            }
#pragma unroll
            for (int nj = 0; nj < 8; nj++) {
                const int chb = (n0g + nj * 8 + qc * 2) * 2;
                __nv_bfloat162 h0 = __floats2bfloat162_rn(c[nj][0], c[nj][1]);
                float2 hf0 = __bfloat1622float2(h0);
                __nv_bfloat162 l0 = __floats2bfloat162_rn(c[nj][0] - hf0.x,
                                                          c[nj][1] - hf0.y);
                __nv_bfloat162 h1 = __floats2bfloat162_rn(c[nj][2], c[nj][3]);
                float2 hf1 = __bfloat1622float2(h1);
                __nv_bfloat162 l1 = __floats2bfloat162_rn(c[nj][2] - hf1.x,
                                                          c[nj][3] - hf1.y);
                const unsigned o0 = skvb_off(m0 + qr,     chb);
                const unsigned o1 = skvb_off(m0 + 8 + qr, chb);
                *(__nv_bfloat162*)(kvh + o0) = h0;
                *(__nv_bfloat162*)(kvl + o0) = l0;
                *(__nv_bfloat162*)(kvh + o1) = h1;
                *(__nv_bfloat162*)(kvl + o1) = l1;
            }
        }
        // cvt X(i+1) regs -> XT; prefetch X(i+2)
        {
            const int nxt = chunk + NPART;
            if (nxt < NCHUNK1) {
#pragma unroll
                for (int i = 0; i < 4; i++) {
                    const int idx = tid + i * 512;
                    const int row = idx >> 5;
                    const int kb  = (idx & 31) << 3;
                    const float4 x = xr[i];
                    __half2 h0 = __floats2half2_rn(x.x, x.y);
                    __half2 h1 = __floats2half2_rn(x.z, x.w);
                    float2 f0 = __half22float2(h0);
                    float2 f1 = __half22float2(h1);
                    __half2 l0 = __floats2half2_rn(x.x - f0.x, x.y - f0.y);
                    __half2 l1 = __floats2half2_rn(x.z - f1.x, x.w - f1.y);
                    const unsigned off = sw_off(row, kb);
                    *(__half2*)(xt + off)             = h0;
                    *(__half2*)(xt + off + 4)         = h1;
                    *(__half2*)(xt + 16384 + off)     = l0;
                    *(__half2*)(xt + 16384 + off + 4) = l1;
                }
                const int nxt2 = nxt + NPART;
                if (nxt2 < NCHUNK1) {
                    const float4* src = (const float4*)X + (size_t)nxt2 * 2048;
#pragma unroll
                    for (int i = 0; i < 4; i++) xr[i] = src[tid + i * 512];
                }
            }
        }
        pend = chunk;
        __syncthreads();   // bar2
    }

    // Epilogue: outer for the final chunk, then flush
    if (pend >= 0) {
        const int bj = pend >> 10;
        if (bj != ob) {
            if (ob >= 0) {
                float* dst = g_part + ((size_t)ob * NPART + blockIdx.x) * 4096
                           + hh2 * 1024 + (dh * 16 + qr) * 32 + eh * 16 + qc * 2;
#pragma unroll
                for (int nt = 0; nt < 2; nt++) {
                    *(float2*)(dst + nt * 8)          = make_float2(co[nt][0], co[nt][1]);
                    *(float2*)(dst + 8 * 32 + nt * 8) = make_float2(co[nt][2], co[nt][3]);
#pragma unroll
                    for (int z = 0; z < 4; z++) co[nt][z] = 0.f;
                }
            }
            ob = bj;
        }
#pragma unroll
        for (int ks = 0; ks < 4; ks++) {
            const unsigned off = (unsigned)(ks * 8192);
            unsigned Ah[4], Al[4], Bh[4], Bl[4];
            ldsm4t(Ah, aOut + off);
            ldsm4t(Al, aOut + 32768u + off);
            ldsm4t(Bh, bOut + off);
            ldsm4t(Bl, bOut + 32768u + off);
            mma_bf16(co[0], Ah[0], Ah[1], Ah[2], Ah[3], Bh[0], Bh[1]);
            mma_bf16(co[0], Ah[0], Ah[1], Ah[2], Ah[3], Bl[0], Bl[1]);
            mma_bf16(co[0], Al[0], Al[1], Al[2], Al[3], Bh[0], Bh[1]);
            mma_bf16(co[1], Ah[0], Ah[1], Ah[2], Ah[3], Bh[2], Bh[3]);
            mma_bf16(co[1], Ah[0], Ah[1], Ah[2], Ah[3], Bl[2], Bl[3]);
            mma_bf16(co[1], Al[0], Al[1], Al[2], Al[3], Bh[2], Bh[3]);
        }
        float* dst = g_part + ((size_t)ob * NPART + blockIdx.x) * 4096
                   + hh2 * 1024 + (dh * 16 + qr) * 32 + eh * 16 + qc * 2;
#pragma unroll
        for (int nt = 0; nt < 2; nt++) {
            *(float2*)(dst + nt * 8)          = make_float2(co[nt][0], co[nt][1]);
            *(float2*)(dst + 8 * 32 + nt * 8) = make_float2(co[nt][2], co[nt][3]);
        }
    }
}

// ============================================================================
// Kernel 2a: reduce 148 per-CTA partials -> g_kv.
// ============================================================================
__global__ void k2a_reduce()
{
    const int gid = blockIdx.x * 256 + threadIdx.x;
    const int b = gid >> 12;
    const int e = gid & 4095;
    const float* src = g_part + (size_t)b * NPART * 4096 + e;
    float s = 0.f;
#pragma unroll 4
    for (int j = 0; j < NPART; j++) s += src[(size_t)j * 4096];
    g_kv[gid] = s;
}

// ============================================================================
// Kernel 2b: Wq_eff_scaled[b][n][c] = sum_d Wq[c][h*32+d] * kv[b][h][d][e]
// (scaled by 65536 relative to the true folded weight; K3 divides at store)
// ============================================================================
__global__ void k2b_fold(const float* __restrict__ Wq)
{
    const int gid = blockIdx.x * 256 + threadIdx.x;
    const int b  = gid >> 14;
    const int r  = gid & 16383;
    const int cp = r >> 7;
    const int co = r & 127;
    const int e  = co >> 2;
    const int h  = co & 3;
    const float* wq = Wq + cp * 128 + h * 32;
    const float* kv = g_kv + b * 4096 + h * 1024 + e;
    float s = 0.f;
#pragma unroll
    for (int d = 0; d < 32; d++) s += wq[d] * kv[d * 32];
    g_wqeff[b * 16384 + co * 128 + cp] = s;
}

// ============================================================================
// Kernel 3 (fp16x2, unchanged from r16): out = (Xh + Xl) @ Ws^T / 65536.
// smem: Ws 32K | pad 32K | Xhi 32K | Xlo 32K | raw 64K = 192 KB
// ============================================================================
#define K3S_W_HI 0
#define K3S_X_HI 65536
#define K3S_X_LO 98304
#define K3S_RAW  131072
#define K3_SMEM  196608
#define K3_OSCALE (1.f / 65536.f)

__device__ __forceinline__ void cvt_tile512_h(const float* __restrict__ src,
                                              char* hi_base, char* lo_base, int tid) {
#pragma unroll
    for (int i = 0; i < 8; i++) {
        const int idx = tid + i * 512;
        const int row = idx >> 5;
        const int kb  = (idx & 31) << 3;
        const float4 x = *(const float4*)(src + idx * 4);
        __half2 h0 = __floats2half2_rn(x.x, x.y);
        __half2 h1 = __floats2half2_rn(x.z, x.w);
        float2 f0 = __half22float2(h0);
        float2 f1 = __half22float2(h1);
        __half2 l0 = __floats2half2_rn(x.x - f0.x, x.y - f0.y);
        __half2 l1 = __floats2half2_rn(x.z - f1.x, x.w - f1.y);
        const unsigned off = sw_off(row, kb);
        *(__half2*)(hi_base + off)     = h0;
        *(__half2*)(hi_base + off + 4) = h1;
        *(__half2*)(lo_base + off)     = l0;
        *(__half2*)(lo_base + off + 4) = l1;
    }
}

__device__ __forceinline__ void cvt_w512_h(const float* __restrict__ src,
                                           char* w_base, int tid) {
    if (tid < 256) {
#pragma unroll
        for (int i = 0; i < 16; i++) {
            const int idx = tid + i * 256;
            const int row = idx >> 5;
            const int kb  = (idx & 31) << 3;
            const float4 x = *(const float4*)(src + idx * 4);
            __half2 h0 = __floats2half2_rn(x.x, x.y);
            __half2 h1 = __floats2half2_rn(x.z, x.w);
            const unsigned off = sw_off(row, kb);
            *(__half2*)(w_base + off)     = h0;
            *(__half2*)(w_base + off + 4) = h1;
        }
    }
}

__global__ void __launch_bounds__(512, 1)
k3_out_mma(const float* __restrict__ X, float* __restrict__ out)
{
    extern __shared__ char smem[];
    const int tid  = threadIdx.x;
    const int lane = tid & 31;
    const int warp = tid >> 5;

    const int m0 = (warp & 3) * 32;
    const int n0 = (warp >> 2) * 32;
    const int qr = lane >> 2;
    const int qc = lane & 3;

    float* raw = (float*)(smem + K3S_RAW);

    const unsigned xh_u = (unsigned)__cvta_generic_to_shared(smem + K3S_X_HI);
    const unsigned wh_u = (unsigned)__cvta_generic_to_shared(smem + K3S_W_HI);

    const int laneK = lane & 16;
    const int bKoff = (lane & 8) << 1;
    unsigned aBase[2], aSw[2], bBase[2], bSw[2];
#pragma unroll
    for (int mi = 0; mi < 2; mi++) {
        const int row = m0 + mi * 16 + (lane & 15);
        aSw[mi] = (unsigned)((row & 7) << 4);
        aBase[mi] = xh_u + row * 256;
    }
#pragma unroll
    for (int p = 0; p < 2; p++) {
        const int row = n0 + p * 16 + ((lane >> 1) & 8) + (lane & 7);
        bSw[p] = (unsigned)((row & 7) << 4);
        bBase[p] = wh_u + row * 256;
    }

    {
        const float* src = X + (size_t)blockIdx.x * 16384;
#pragma unroll
        for (int i = 0; i < 8; i++)
            cp16(raw + (tid + i * 512) * 4, src + (tid + i * 512) * 4);
        cp_commit();
    }

    int cur_b = -1;
    for (int chunk = blockIdx.x; chunk < NCHUNK3; chunk += NPART) {
        const int b = chunk >> 9;

        cp_wait_all();
        __syncthreads();

        if (b != cur_b) {
            cvt_w512_h(g_wqeff + b * 16384, smem + K3S_W_HI, tid);
            cur_b = b;
        }
        cvt_tile512_h(raw, smem + K3S_X_HI, smem + K3S_X_LO, tid);
        __syncthreads();

        {
            const int nxt = chunk + NPART;
            if (nxt < NCHUNK3) {
                const float* src = X + (size_t)nxt * 16384;
#pragma unroll
                for (int i = 0; i < 8; i++)
                    cp16(raw + (tid + i * 512) * 4, src + (tid + i * 512) * 4);
                cp_commit();
            }
        }

        float c[2][4][4];
#pragma unroll
        for (int mi = 0; mi < 2; mi++)
#pragma unroll
            for (int nj = 0; nj < 4; nj++)
#pragma unroll
                for (int z = 0; z < 4; z++) c[mi][nj][z] = 0.f;

#pragma unroll
        for (int ks = 0; ks < 8; ks++) {
            const int kb = ks * 32;
            unsigned ah[2][4], al[2][4], bh[4][2];
#pragma unroll
            for (int mi = 0; mi < 2; mi++) {
                const unsigned off = (unsigned)(kb + laneK) ^ aSw[mi];
                ldsm4(ah[mi], aBase[mi] + off);
                ldsm4(al[mi], aBase[mi] + 32768u + off);
            }
#pragma unroll
            for (int p = 0; p < 2; p++) {
                const unsigned off = (unsigned)(kb + bKoff) ^ bSw[p];
                unsigned t[4];
                ldsm4(t, bBase[p] + off);
                bh[2 * p][0] = t[0]; bh[2 * p][1] = t[1];
                bh[2 * p + 1][0] = t[2]; bh[2 * p + 1][1] = t[3];
            }
#pragma unroll
            for (int mi = 0; mi < 2; mi++)
#pragma unroll
                for (int nj = 0; nj < 4; nj++) {
                    mma_f16(c[mi][nj], ah[mi][0], ah[mi][1], ah[mi][2], ah[mi][3],
                            bh[nj][0], bh[nj][1]);
                    mma_f16(c[mi][nj], al[mi][0], al[mi][1], al[mi][2], al[mi][3],
                            bh[nj][0], bh[nj][1]);
                }
        }

        float* obase = out + (size_t)chunk * 16384;
#pragma unroll
        for (int mi = 0; mi < 2; mi++) {
            const int r = m0 + mi * 16 + qr;
#pragma unroll
            for (int nj = 0; nj < 4; nj++) {
                const int col = n0 + nj * 8 + qc * 2;
                *(float2*)(obase + r * 128 + col) =
                    make_float2(c[mi][nj][0] * K3_OSCALE, c[mi][nj][1] * K3_OSCALE);
                *(float2*)(obase + (r + 8) * 128 + col) =
                    make_float2(c[mi][nj][2] * K3_OSCALE, c[mi][nj][3] * K3_OSCALE);
            }
        }
    }
}

// ============================================================================
extern "C" void kernel_launch(void* const* d_in, const int* in_sizes, int n_in,
                              void* d_out, int out_size)
{
    (void)in_sizes; (void)n_in; (void)out_size;
    const float* X     = (const float*)d_in[0];
    const float* Wq    = (const float*)d_in[1];
    const float* Wk    = (const float*)d_in[2];
    const float* Wv    = (const float*)d_in[3];
    const float* gamma = (const float*)d_in[4];
    const float* beta  = (const float*)d_in[5];
    float* out = (float*)d_out;

    cudaFuncSetAttribute(k1_kv_mma, cudaFuncAttributeMaxDynamicSharedMemorySize,
                         K1_SMEM);    // 162 KB
    cudaFuncSetAttribute(k3_out_mma, cudaFuncAttributeMaxDynamicSharedMemorySize,
                         K3_SMEM);    // 192 KB

    k1_kv_mma<<<NPART, 512, K1_SMEM>>>(X, Wk, Wv, gamma, beta);
    k2a_reduce<<<64, 256>>>();
    k2b_fold<<<256, 256>>>(Wq);
    k3_out_mma<<<NPART, 512, K3_SMEM>>>(X, out);
}